// round 13
// baseline (speedup 1.0000x reference)
#include <cuda_runtime.h>
#include <cuda_bf16.h>
#include <cstdint>

#define N_TOK 4096
#define TD    384
#define KNB   64
#define PD    128
#define HD    256
#define LN_EPS 1e-5f

// ---------------- device scratch (no allocs allowed) ----------------
__device__ __align__(16) float g_proj[N_TOK * 256];   // [n][0:128]=xp1, [128:256]=xp2
// Weight fragments for mma.sync.m16n8k16 (bf16), packed as uint4 nt-pairs:
__device__ __align__(16) uint4 g_W1f4[8 * 16 * 32];   // K=128 (8 kt) x N=256 (16 np)
__device__ __align__(16) uint4 g_W2f4[16 * 8 * 32];   // K=256 (16 kt) x N=128 (8 np)

// bool inputs arrive as 4-byte words (int32/float32); nonzero = true.
__device__ __forceinline__ bool bval(const unsigned int* b, int i) { return b[i] != 0u; }

__device__ __forceinline__ uint32_t pack2bf(float a, float b) {
    __nv_bfloat162 t = __floats2bfloat162_rn(a, b);
    return *reinterpret_cast<uint32_t*>(&t);
}

__device__ __forceinline__ uint32_t smem_u32(const void* p) {
    uint32_t a;
    asm("{ .reg .u64 t; cvta.to.shared.u64 t, %1; cvt.u32.u64 %0, t; }" : "=r"(a) : "l"(p));
    return a;
}

__device__ __forceinline__ void ldsm_x4(uint32_t* a, uint32_t addr) {
    asm volatile("ldmatrix.sync.aligned.m8n8.x4.shared.b16 {%0,%1,%2,%3}, [%4];"
                 : "=r"(a[0]), "=r"(a[1]), "=r"(a[2]), "=r"(a[3]) : "r"(addr));
}

__device__ __forceinline__ void mma16816(float* c, const uint32_t* a, uint32_t b0, uint32_t b1) {
    asm volatile(
        "mma.sync.aligned.m16n8k16.row.col.f32.bf16.bf16.f32 "
        "{%0,%1,%2,%3}, {%4,%5,%6,%7}, {%8,%9}, {%0,%1,%2,%3};"
        : "+f"(c[0]), "+f"(c[1]), "+f"(c[2]), "+f"(c[3])
        : "r"(a[0]), "r"(a[1]), "r"(a[2]), "r"(a[3]), "r"(b0), "r"(b1));
}

// ---------------- kernel 1: fused proj + weight packing --------------------
// blocks [0,1024): proj, 8 token-rows x 128 p-columns per block.
//   (column split doubles block count at constant chip-wide Wx traffic;
//    measured trend: fused_k is parallelism-bound, more blocks -> faster)
// blocks [1024,1056): pack W1/W2 fragments
#define PROJ_ROWS   8
#define PROJ_BLOCKS ((N_TOK / PROJ_ROWS) * 2)   // 1024
#define PACK_BLOCKS 32

__global__ __launch_bounds__(256) void fused_k(const float* __restrict__ x,
                                               const unsigned int* __restrict__ mask,
                                               const float* __restrict__ ln_g,
                                               const float* __restrict__ ln_b,
                                               const float* __restrict__ Wx,
                                               const float* __restrict__ W1,
                                               const float* __restrict__ W2) {
    __shared__ float xs[PROJ_ROWS * TD];   // 12 KB
    int tid = threadIdx.x;

    if (blockIdx.x >= PROJ_BLOCKS) {
        // ---- weight fragment packing (uint4 nt-pairs) ----
        int t0 = (blockIdx.x - PROJ_BLOCKS) * 256 + tid;
        int stride = PACK_BLOCKS * 256;
        for (int e = t0; e < 8 * 16 * 32; e += stride) {
            int lane = e & 31, np = (e >> 5) & 15, kt = e >> 9;
            int tig = lane & 3, g = lane >> 2;
            int j0 = (2 * np) * 8 + g;
            int j1 = (2 * np + 1) * 8 + g;
            int k0 = kt * 16 + tig * 2;
            g_W1f4[e] = make_uint4(
                pack2bf(W1[k0 * HD + j0], W1[(k0 + 1) * HD + j0]),
                pack2bf(W1[(k0 + 8) * HD + j0], W1[(k0 + 9) * HD + j0]),
                pack2bf(W1[k0 * HD + j1], W1[(k0 + 1) * HD + j1]),
                pack2bf(W1[(k0 + 8) * HD + j1], W1[(k0 + 9) * HD + j1]));
        }
        for (int e = t0; e < 16 * 8 * 32; e += stride) {
            int lane = e & 31, np = (e >> 5) & 7, kt = e >> 8;
            int tig = lane & 3, g = lane >> 2;
            int i0 = (2 * np) * 8 + g;
            int i1 = (2 * np + 1) * 8 + g;
            int k0 = kt * 16 + tig * 2;
            g_W2f4[e] = make_uint4(
                pack2bf(W2[k0 * PD + i0], W2[(k0 + 1) * PD + i0]),
                pack2bf(W2[(k0 + 8) * PD + i0], W2[(k0 + 9) * PD + i0]),
                pack2bf(W2[k0 * PD + i1], W2[(k0 + 1) * PD + i1]),
                pack2bf(W2[(k0 + 8) * PD + i1], W2[(k0 + 9) * PD + i1]));
        }
        return;
    }

    // ---- proj = LN(x*mask) @ Wx ; this block: 8 rows x 128 p-cols ----
    int rg = blockIdx.x >> 1;          // row group
    int ch = blockIdx.x & 1;           // column half
    int n0 = rg * PROJ_ROWS;
    for (int i = tid; i < PROJ_ROWS * TD; i += 256) {
        int r = i / TD;
        float mf = bval(mask, n0 + r) ? 1.0f : 0.0f;
        xs[i] = x[(size_t)n0 * TD + i] * mf;
    }
    __syncthreads();
    {
        int warp = tid >> 5, lane = tid & 31;
        int r = warp;
        float v[12];
        float s = 0.0f, s2 = 0.0f;
#pragma unroll
        for (int q = 0; q < 12; q++) {
            v[q] = xs[r * TD + lane + q * 32];
            s += v[q]; s2 += v[q] * v[q];
        }
#pragma unroll
        for (int o = 16; o; o >>= 1) {
            s  += __shfl_xor_sync(0xffffffffu, s, o);
            s2 += __shfl_xor_sync(0xffffffffu, s2, o);
        }
        float mu = s * (1.0f / (float)TD);
        float rstd = rsqrtf(s2 * (1.0f / (float)TD) - mu * mu + LN_EPS);
#pragma unroll
        for (int q = 0; q < 12; q++) {
            int t = lane + q * 32;
            xs[r * TD + t] = (v[q] - mu) * rstd * ln_g[t] + ln_b[t];
        }
    }
    __syncthreads();

    // GEMV: thread -> column p (128 cols), row-half rh (4 rows each)
    int p  = ch * 128 + (tid & 127);
    int rh = tid >> 7;                 // 0: rows 0-3, 1: rows 4-7
    float acc[4];
#pragma unroll
    for (int r = 0; r < 4; r++) acc[r] = 0.0f;
    const float4* xs4 = (const float4*)xs;
    for (int t4 = 0; t4 < TD / 4; t4++) {
        float w0 = Wx[(t4 * 4 + 0) * 256 + p];
        float w1 = Wx[(t4 * 4 + 1) * 256 + p];
        float w2 = Wx[(t4 * 4 + 2) * 256 + p];
        float w3 = Wx[(t4 * 4 + 3) * 256 + p];
#pragma unroll
        for (int rr = 0; rr < 4; rr++) {
            float4 xv = xs4[(rh * 4 + rr) * (TD / 4) + t4];
            acc[rr] = fmaf(w0, xv.x, acc[rr]);
            acc[rr] = fmaf(w1, xv.y, acc[rr]);
            acc[rr] = fmaf(w2, xv.z, acc[rr]);
            acc[rr] = fmaf(w3, xv.w, acc[rr]);
        }
    }
#pragma unroll
    for (int rr = 0; rr < 4; rr++)
        g_proj[(size_t)(n0 + rh * 4 + rr) * 256 + p] = acc[rr];
}

// ---------------- kernel 2: fused pair update + transition ------------------
// FROZEN: exact R11 configuration (best measured 167.2 us, regs 62, occ 4/SM).
// One CTA = 32 pair-rows. 256 threads = 8 warps. grid = 8192.
#define SM_Z    0
#define SM_ZLN  16896
#define SM_H    25600
#define SM_XP2  42496
#define SM_PM   43008
#define SM_IDX  43136
#define SM_TOT  43264
#define ZSTR    132
#define LSTR    136
#define HSTR    264

__global__ __launch_bounds__(256, 4) void main_k(const float* __restrict__ pair_rep,
                                                 const unsigned int* __restrict__ mask,
                                                 const int* __restrict__ nbr,
                                                 const unsigned int* __restrict__ slot,
                                                 const float* __restrict__ t_g,
                                                 const float* __restrict__ t_b,
                                                 const float* __restrict__ b1,
                                                 const float* __restrict__ b2,
                                                 float* __restrict__ out) {
    extern __shared__ char smb[];
    float* z_s   = (float*)(smb + SM_Z);
    char*  zln_b = smb + SM_ZLN;
    char*  h_b   = smb + SM_H;
    float* xp2_s = (float*)(smb + SM_XP2);
    float* pm_s  = (float*)(smb + SM_PM);
    int*   idx_s = (int*)(smb + SM_IDX);

    int tid  = threadIdx.x;
    int warp = tid >> 5, lane = tid & 31;
    int g    = lane >> 2, tig = lane & 3;
    int n     = blockIdx.x >> 1;
    int kbase = (blockIdx.x & 1) * 32;

    if (tid < 128) {
        xp2_s[tid] = g_proj[n * 256 + 128 + tid];
    } else if (tid < 160) {
        int r = tid - 128;
        int k = kbase + r;
        int idx = nbr[n * KNB + k];
        idx_s[r] = idx;
        bool pm = bval(mask, n) && bval(mask, idx) && bval(slot, n * KNB + k);
        pm_s[r] = pm ? 1.0f : 0.0f;
    }
    __syncthreads();

    // ---- z = (pair_rep + xp2 + xp1[nbr]) * pm ----
    {
        int pc = lane * 4;
        int rb = warp;
#pragma unroll
        for (int it = 0; it < 4; it++) {
            int r = it * 8 + rb;
            const float4 pr = *(const float4*)&pair_rep[((size_t)(n * KNB + kbase + r)) * PD + pc];
            const float4 xj = *(const float4*)&g_proj[idx_s[r] * 256 + pc];
            const float4 xo = *(const float4*)&xp2_s[pc];
            float pm = pm_s[r];
            float4 z;
            z.x = (pr.x + xo.x + xj.x) * pm;
            z.y = (pr.y + xo.y + xj.y) * pm;
            z.z = (pr.z + xo.z + xj.z) * pm;
            z.w = (pr.w + xo.w + xj.w) * pm;
            *(float4*)&z_s[r * ZSTR + pc] = z;
        }
    }
    __syncthreads();

    // ---- LayerNorm(z) -> zln (bf16), single-pass sum/sumsq ----
    {
        float4 tg4 = *(const float4*)&t_g[4 * lane];
        float4 tb4 = *(const float4*)&t_b[4 * lane];
#pragma unroll
        for (int rr = 0; rr < 4; rr++) {
            int r = warp * 4 + rr;
            float4 v = *(const float4*)&z_s[r * ZSTR + 4 * lane];
            float s  = v.x + v.y + v.z + v.w;
            float s2 = v.x * v.x + v.y * v.y + v.z * v.z + v.w * v.w;
#pragma unroll
            for (int o = 16; o; o >>= 1) {
                s  += __shfl_xor_sync(0xffffffffu, s, o);
                s2 += __shfl_xor_sync(0xffffffffu, s2, o);
            }
            float mu  = s * (1.0f / 128.0f);
            float var = s2 * (1.0f / 128.0f) - mu * mu;
            float rstd = rsqrtf(var + LN_EPS);
            uint2 pk;
            pk.x = pack2bf((v.x - mu) * rstd * tg4.x + tb4.x,
                           (v.y - mu) * rstd * tg4.y + tb4.y);
            pk.y = pack2bf((v.z - mu) * rstd * tg4.z + tb4.z,
                           (v.w - mu) * rstd * tg4.w + tb4.w);
            *(uint2*)(zln_b + r * (LSTR * 2) + 8 * lane) = pk;
        }
    }
    __syncthreads();

    // ---- phase 1: h = relu(zln @ W1 + b1) ; warp covers 32 N-cols ----
    {
        uint32_t zln_u = smem_u32(zln_b);
        float c1[2][4][4];
#pragma unroll
        for (int mt = 0; mt < 2; mt++)
#pragma unroll
            for (int nt = 0; nt < 4; nt++)
#pragma unroll
                for (int q = 0; q < 4; q++) c1[mt][nt][q] = 0.0f;

#pragma unroll 2
        for (int kt = 0; kt < 8; kt++) {
            uint32_t a0[4], a1[4];
            {
                uint32_t base = zln_u + ((lane & 15) * LSTR + kt * 16 + (lane >> 4) * 8) * 2;
                ldsm_x4(a0, base);
                ldsm_x4(a1, base + 16 * LSTR * 2);
            }
#pragma unroll
            for (int np = 0; np < 2; np++) {
                uint4 w = g_W1f4[((kt * 16) + (warp * 2 + np)) * 32 + lane];
                mma16816(c1[0][2 * np],     a0, w.x, w.y);
                mma16816(c1[1][2 * np],     a1, w.x, w.y);
                mma16816(c1[0][2 * np + 1], a0, w.z, w.w);
                mma16816(c1[1][2 * np + 1], a1, w.z, w.w);
            }
        }
#pragma unroll
        for (int nt = 0; nt < 4; nt++) {
            int j0 = warp * 32 + nt * 8 + tig * 2;
            float2 bb = *(const float2*)&b1[j0];
#pragma unroll
            for (int mt = 0; mt < 2; mt++) {
                int r0 = mt * 16 + g;
                float* c = c1[mt][nt];
                *(uint32_t*)(h_b + r0 * (HSTR * 2) + j0 * 2) =
                    pack2bf(fmaxf(c[0] + bb.x, 0.0f), fmaxf(c[1] + bb.y, 0.0f));
                *(uint32_t*)(h_b + (r0 + 8) * (HSTR * 2) + j0 * 2) =
                    pack2bf(fmaxf(c[2] + bb.x, 0.0f), fmaxf(c[3] + bb.y, 0.0f));
            }
        }
    }
    __syncthreads();

    // ---- phase 2: out = (z + h @ W2 + b2) * pm ; warp covers 16 N-cols ----
    {
        uint32_t h_u = smem_u32(h_b);
        float c2[2][2][4];
#pragma unroll
        for (int mt = 0; mt < 2; mt++)
#pragma unroll
            for (int nt = 0; nt < 2; nt++)
#pragma unroll
                for (int q = 0; q < 4; q++) c2[mt][nt][q] = 0.0f;

#pragma unroll 4
        for (int kt = 0; kt < 16; kt++) {
            uint32_t a0[4], a1[4];
            {
                uint32_t base = h_u + ((lane & 15) * HSTR + kt * 16 + (lane >> 4) * 8) * 2;
                ldsm_x4(a0, base);
                ldsm_x4(a1, base + 16 * HSTR * 2);
            }
            {
                uint4 w = g_W2f4[((kt * 8) + warp) * 32 + lane];
                mma16816(c2[0][0], a0, w.x, w.y);
                mma16816(c2[1][0], a1, w.x, w.y);
                mma16816(c2[0][1], a0, w.z, w.w);
                mma16816(c2[1][1], a1, w.z, w.w);
            }
        }
#pragma unroll
        for (int nt = 0; nt < 2; nt++) {
            int i0 = warp * 16 + nt * 8 + tig * 2;
            float2 bb = *(const float2*)&b2[i0];
#pragma unroll
            for (int mt = 0; mt < 2; mt++) {
                float* c = c2[mt][nt];
                int r0 = mt * 16 + g;
                {
                    float pm = pm_s[r0];
                    float2 zz = *(const float2*)&z_s[r0 * ZSTR + i0];
                    float2 o;
                    o.x = (zz.x + c[0] + bb.x) * pm;
                    o.y = (zz.y + c[1] + bb.y) * pm;
                    *(float2*)&out[((size_t)(n * KNB + kbase + r0)) * PD + i0] = o;
                }
                {
                    int r1 = r0 + 8;
                    float pm = pm_s[r1];
                    float2 zz = *(const float2*)&z_s[r1 * ZSTR + i0];
                    float2 o;
                    o.x = (zz.x + c[2] + bb.x) * pm;
                    o.y = (zz.y + c[3] + bb.y) * pm;
                    *(float2*)&out[((size_t)(n * KNB + kbase + r1)) * PD + i0] = o;
                }
            }
        }
    }
}

// ---------------- launcher ----------------
extern "C" void kernel_launch(void* const* d_in, const int* in_sizes, int n_in,
                              void* d_out, int out_size) {
    const float*        x        = (const float*)d_in[0];
    const float*        pair_rep = (const float*)d_in[1];
    const unsigned int* mask     = (const unsigned int*)d_in[2];
    const int*          nbr      = (const int*)d_in[3];
    const unsigned int* slot     = (const unsigned int*)d_in[4];
    const float*        ln_g     = (const float*)d_in[5];
    const float*        ln_b     = (const float*)d_in[6];
    const float*        Wx       = (const float*)d_in[7];
    const float*        t_g      = (const float*)d_in[8];
    const float*        t_b      = (const float*)d_in[9];
    const float*        W1       = (const float*)d_in[10];
    const float*        b1       = (const float*)d_in[11];
    const float*        W2       = (const float*)d_in[12];
    const float*        b2       = (const float*)d_in[13];
    float*              out      = (float*)d_out;

    fused_k<<<PROJ_BLOCKS + PACK_BLOCKS, 256>>>(x, mask, ln_g, ln_b, Wx, W1, W2);

    cudaFuncSetAttribute(main_k, cudaFuncAttributeMaxDynamicSharedMemorySize, SM_TOT);
    main_k<<<2 * N_TOK, 256, SM_TOT>>>(pair_rep, mask, nbr, slot,
                                       t_g, t_b, b1, b2, out);
}

// round 14
// speedup vs baseline: 1.0951x; 1.0951x over previous
#include <cuda_runtime.h>
#include <cuda_bf16.h>
#include <cstdint>

#define N_TOK 4096
#define TD    384
#define KNB   64
#define PD    128
#define HD    256
#define LN_EPS 1e-5f

// ---------------- device scratch (no allocs allowed) ----------------
__device__ __align__(16) float g_proj[N_TOK * 256];   // [n][0:128]=xp1, [128:256]=xp2
// Weight fragments for mma.sync.m16n8k16 (bf16), packed as uint4 nt-pairs:
__device__ __align__(16) uint4 g_W1f4[8 * 16 * 32];   // K=128 (8 kt) x N=256 (16 np)
__device__ __align__(16) uint4 g_W2f4[16 * 8 * 32];   // K=256 (16 kt) x N=128 (8 np)

// bool inputs arrive as 4-byte words (int32/float32); nonzero = true.
__device__ __forceinline__ bool bval(const unsigned int* b, int i) { return b[i] != 0u; }

__device__ __forceinline__ uint32_t pack2bf(float a, float b) {
    __nv_bfloat162 t = __floats2bfloat162_rn(a, b);
    return *reinterpret_cast<uint32_t*>(&t);
}

__device__ __forceinline__ uint32_t smem_u32(const void* p) {
    uint32_t a;
    asm("{ .reg .u64 t; cvta.to.shared.u64 t, %1; cvt.u32.u64 %0, t; }" : "=r"(a) : "l"(p));
    return a;
}

__device__ __forceinline__ void ldsm_x4(uint32_t* a, uint32_t addr) {
    asm volatile("ldmatrix.sync.aligned.m8n8.x4.shared.b16 {%0,%1,%2,%3}, [%4];"
                 : "=r"(a[0]), "=r"(a[1]), "=r"(a[2]), "=r"(a[3]) : "r"(addr));
}

__device__ __forceinline__ void mma16816(float* c, const uint32_t* a, uint32_t b0, uint32_t b1) {
    asm volatile(
        "mma.sync.aligned.m16n8k16.row.col.f32.bf16.bf16.f32 "
        "{%0,%1,%2,%3}, {%4,%5,%6,%7}, {%8,%9}, {%0,%1,%2,%3};"
        : "+f"(c[0]), "+f"(c[1]), "+f"(c[2]), "+f"(c[3])
        : "r"(a[0]), "r"(a[1]), "r"(a[2]), "r"(a[3]), "r"(b0), "r"(b1));
}

// ---------------- kernel 1: fused proj + weight packing --------------------
// PROVEN CONFIG (rest = 53.8-54.0 us, measured twice in R7/R12):
// blocks [0,512): proj, 8 token-rows x full 256 p-cols, 8 accumulators/thread
// blocks [512,544): pack W1/W2 fragments
#define PROJ_ROWS   8
#define PROJ_BLOCKS (N_TOK / PROJ_ROWS)    // 512
#define PACK_BLOCKS 32

__global__ __launch_bounds__(256) void fused_k(const float* __restrict__ x,
                                               const unsigned int* __restrict__ mask,
                                               const float* __restrict__ ln_g,
                                               const float* __restrict__ ln_b,
                                               const float* __restrict__ Wx,
                                               const float* __restrict__ W1,
                                               const float* __restrict__ W2) {
    __shared__ float xs[PROJ_ROWS * TD];   // 12 KB
    int tid = threadIdx.x;

    if (blockIdx.x >= PROJ_BLOCKS) {
        // ---- weight fragment packing (uint4 nt-pairs) ----
        int t0 = (blockIdx.x - PROJ_BLOCKS) * 256 + tid;
        int stride = PACK_BLOCKS * 256;
        for (int e = t0; e < 8 * 16 * 32; e += stride) {
            int lane = e & 31, np = (e >> 5) & 15, kt = e >> 9;
            int tig = lane & 3, g = lane >> 2;
            int j0 = (2 * np) * 8 + g;
            int j1 = (2 * np + 1) * 8 + g;
            int k0 = kt * 16 + tig * 2;
            g_W1f4[e] = make_uint4(
                pack2bf(W1[k0 * HD + j0], W1[(k0 + 1) * HD + j0]),
                pack2bf(W1[(k0 + 8) * HD + j0], W1[(k0 + 9) * HD + j0]),
                pack2bf(W1[k0 * HD + j1], W1[(k0 + 1) * HD + j1]),
                pack2bf(W1[(k0 + 8) * HD + j1], W1[(k0 + 9) * HD + j1]));
        }
        for (int e = t0; e < 16 * 8 * 32; e += stride) {
            int lane = e & 31, np = (e >> 5) & 7, kt = e >> 8;
            int tig = lane & 3, g = lane >> 2;
            int i0 = (2 * np) * 8 + g;
            int i1 = (2 * np + 1) * 8 + g;
            int k0 = kt * 16 + tig * 2;
            g_W2f4[e] = make_uint4(
                pack2bf(W2[k0 * PD + i0], W2[(k0 + 1) * PD + i0]),
                pack2bf(W2[(k0 + 8) * PD + i0], W2[(k0 + 9) * PD + i0]),
                pack2bf(W2[k0 * PD + i1], W2[(k0 + 1) * PD + i1]),
                pack2bf(W2[(k0 + 8) * PD + i1], W2[(k0 + 9) * PD + i1]));
        }
        return;
    }

    // ---- proj = LN(x*mask) @ Wx ----
    int n0 = blockIdx.x * PROJ_ROWS;
    for (int i = tid; i < PROJ_ROWS * TD; i += 256) {
        int r = i / TD;
        float mf = bval(mask, n0 + r) ? 1.0f : 0.0f;
        xs[i] = x[(size_t)n0 * TD + i] * mf;
    }
    __syncthreads();
    {
        int warp = tid >> 5, lane = tid & 31;
        int r = warp;
        float v[12];
        float s = 0.0f, s2 = 0.0f;
#pragma unroll
        for (int q = 0; q < 12; q++) {
            v[q] = xs[r * TD + lane + q * 32];
            s += v[q]; s2 += v[q] * v[q];
        }
#pragma unroll
        for (int o = 16; o; o >>= 1) {
            s  += __shfl_xor_sync(0xffffffffu, s, o);
            s2 += __shfl_xor_sync(0xffffffffu, s2, o);
        }
        float mu = s * (1.0f / (float)TD);
        float rstd = rsqrtf(s2 * (1.0f / (float)TD) - mu * mu + LN_EPS);
#pragma unroll
        for (int q = 0; q < 12; q++) {
            int t = lane + q * 32;
            xs[r * TD + t] = (v[q] - mu) * rstd * ln_g[t] + ln_b[t];
        }
    }
    __syncthreads();

    float acc[PROJ_ROWS];
#pragma unroll
    for (int r = 0; r < PROJ_ROWS; r++) acc[r] = 0.0f;
    const float4* xs4 = (const float4*)xs;
    for (int t4 = 0; t4 < TD / 4; t4++) {
        float w0 = Wx[(t4 * 4 + 0) * 256 + tid];
        float w1 = Wx[(t4 * 4 + 1) * 256 + tid];
        float w2 = Wx[(t4 * 4 + 2) * 256 + tid];
        float w3 = Wx[(t4 * 4 + 3) * 256 + tid];
#pragma unroll
        for (int r = 0; r < PROJ_ROWS; r++) {
            float4 xv = xs4[r * (TD / 4) + t4];
            acc[r] = fmaf(w0, xv.x, acc[r]);
            acc[r] = fmaf(w1, xv.y, acc[r]);
            acc[r] = fmaf(w2, xv.z, acc[r]);
            acc[r] = fmaf(w3, xv.w, acc[r]);
        }
    }
#pragma unroll
    for (int r = 0; r < PROJ_ROWS; r++) g_proj[(size_t)(n0 + r) * 256 + tid] = acc[r];
}

// ---------------- kernel 2: fused pair update + transition ------------------
// FROZEN: exact R11/R13 configuration (166.8-167.2 us, 3 consistent runs).
// One CTA = 32 pair-rows. 256 threads = 8 warps. grid = 8192.
#define SM_Z    0
#define SM_ZLN  16896
#define SM_H    25600
#define SM_XP2  42496
#define SM_PM   43008
#define SM_IDX  43136
#define SM_TOT  43264
#define ZSTR    132
#define LSTR    136
#define HSTR    264

__global__ __launch_bounds__(256, 4) void main_k(const float* __restrict__ pair_rep,
                                                 const unsigned int* __restrict__ mask,
                                                 const int* __restrict__ nbr,
                                                 const unsigned int* __restrict__ slot,
                                                 const float* __restrict__ t_g,
                                                 const float* __restrict__ t_b,
                                                 const float* __restrict__ b1,
                                                 const float* __restrict__ b2,
                                                 float* __restrict__ out) {
    extern __shared__ char smb[];
    float* z_s   = (float*)(smb + SM_Z);
    char*  zln_b = smb + SM_ZLN;
    char*  h_b   = smb + SM_H;
    float* xp2_s = (float*)(smb + SM_XP2);
    float* pm_s  = (float*)(smb + SM_PM);
    int*   idx_s = (int*)(smb + SM_IDX);

    int tid  = threadIdx.x;
    int warp = tid >> 5, lane = tid & 31;
    int g    = lane >> 2, tig = lane & 3;
    int n     = blockIdx.x >> 1;
    int kbase = (blockIdx.x & 1) * 32;

    if (tid < 128) {
        xp2_s[tid] = g_proj[n * 256 + 128 + tid];
    } else if (tid < 160) {
        int r = tid - 128;
        int k = kbase + r;
        int idx = nbr[n * KNB + k];
        idx_s[r] = idx;
        bool pm = bval(mask, n) && bval(mask, idx) && bval(slot, n * KNB + k);
        pm_s[r] = pm ? 1.0f : 0.0f;
    }
    __syncthreads();

    // ---- z = (pair_rep + xp2 + xp1[nbr]) * pm ----
    {
        int pc = lane * 4;
        int rb = warp;
#pragma unroll
        for (int it = 0; it < 4; it++) {
            int r = it * 8 + rb;
            const float4 pr = *(const float4*)&pair_rep[((size_t)(n * KNB + kbase + r)) * PD + pc];
            const float4 xj = *(const float4*)&g_proj[idx_s[r] * 256 + pc];
            const float4 xo = *(const float4*)&xp2_s[pc];
            float pm = pm_s[r];
            float4 z;
            z.x = (pr.x + xo.x + xj.x) * pm;
            z.y = (pr.y + xo.y + xj.y) * pm;
            z.z = (pr.z + xo.z + xj.z) * pm;
            z.w = (pr.w + xo.w + xj.w) * pm;
            *(float4*)&z_s[r * ZSTR + pc] = z;
        }
    }
    __syncthreads();

    // ---- LayerNorm(z) -> zln (bf16), single-pass sum/sumsq ----
    {
        float4 tg4 = *(const float4*)&t_g[4 * lane];
        float4 tb4 = *(const float4*)&t_b[4 * lane];
#pragma unroll
        for (int rr = 0; rr < 4; rr++) {
            int r = warp * 4 + rr;
            float4 v = *(const float4*)&z_s[r * ZSTR + 4 * lane];
            float s  = v.x + v.y + v.z + v.w;
            float s2 = v.x * v.x + v.y * v.y + v.z * v.z + v.w * v.w;
#pragma unroll
            for (int o = 16; o; o >>= 1) {
                s  += __shfl_xor_sync(0xffffffffu, s, o);
                s2 += __shfl_xor_sync(0xffffffffu, s2, o);
            }
            float mu  = s * (1.0f / 128.0f);
            float var = s2 * (1.0f / 128.0f) - mu * mu;
            float rstd = rsqrtf(var + LN_EPS);
            uint2 pk;
            pk.x = pack2bf((v.x - mu) * rstd * tg4.x + tb4.x,
                           (v.y - mu) * rstd * tg4.y + tb4.y);
            pk.y = pack2bf((v.z - mu) * rstd * tg4.z + tb4.z,
                           (v.w - mu) * rstd * tg4.w + tb4.w);
            *(uint2*)(zln_b + r * (LSTR * 2) + 8 * lane) = pk;
        }
    }
    __syncthreads();

    // ---- phase 1: h = relu(zln @ W1 + b1) ; warp covers 32 N-cols ----
    {
        uint32_t zln_u = smem_u32(zln_b);
        float c1[2][4][4];
#pragma unroll
        for (int mt = 0; mt < 2; mt++)
#pragma unroll
            for (int nt = 0; nt < 4; nt++)
#pragma unroll
                for (int q = 0; q < 4; q++) c1[mt][nt][q] = 0.0f;

#pragma unroll 2
        for (int kt = 0; kt < 8; kt++) {
            uint32_t a0[4], a1[4];
            {
                uint32_t base = zln_u + ((lane & 15) * LSTR + kt * 16 + (lane >> 4) * 8) * 2;
                ldsm_x4(a0, base);
                ldsm_x4(a1, base + 16 * LSTR * 2);
            }
#pragma unroll
            for (int np = 0; np < 2; np++) {
                uint4 w = g_W1f4[((kt * 16) + (warp * 2 + np)) * 32 + lane];
                mma16816(c1[0][2 * np],     a0, w.x, w.y);
                mma16816(c1[1][2 * np],     a1, w.x, w.y);
                mma16816(c1[0][2 * np + 1], a0, w.z, w.w);
                mma16816(c1[1][2 * np + 1], a1, w.z, w.w);
            }
        }
#pragma unroll
        for (int nt = 0; nt < 4; nt++) {
            int j0 = warp * 32 + nt * 8 + tig * 2;
            float2 bb = *(const float2*)&b1[j0];
#pragma unroll
            for (int mt = 0; mt < 2; mt++) {
                int r0 = mt * 16 + g;
                float* c = c1[mt][nt];
                *(uint32_t*)(h_b + r0 * (HSTR * 2) + j0 * 2) =
                    pack2bf(fmaxf(c[0] + bb.x, 0.0f), fmaxf(c[1] + bb.y, 0.0f));
                *(uint32_t*)(h_b + (r0 + 8) * (HSTR * 2) + j0 * 2) =
                    pack2bf(fmaxf(c[2] + bb.x, 0.0f), fmaxf(c[3] + bb.y, 0.0f));
            }
        }
    }
    __syncthreads();

    // ---- phase 2: out = (z + h @ W2 + b2) * pm ; warp covers 16 N-cols ----
    {
        uint32_t h_u = smem_u32(h_b);
        float c2[2][2][4];
#pragma unroll
        for (int mt = 0; mt < 2; mt++)
#pragma unroll
            for (int nt = 0; nt < 2; nt++)
#pragma unroll
                for (int q = 0; q < 4; q++) c2[mt][nt][q] = 0.0f;

#pragma unroll 4
        for (int kt = 0; kt < 16; kt++) {
            uint32_t a0[4], a1[4];
            {
                uint32_t base = h_u + ((lane & 15) * HSTR + kt * 16 + (lane >> 4) * 8) * 2;
                ldsm_x4(a0, base);
                ldsm_x4(a1, base + 16 * HSTR * 2);
            }
            {
                uint4 w = g_W2f4[((kt * 8) + warp) * 32 + lane];
                mma16816(c2[0][0], a0, w.x, w.y);
                mma16816(c2[1][0], a1, w.x, w.y);
                mma16816(c2[0][1], a0, w.z, w.w);
                mma16816(c2[1][1], a1, w.z, w.w);
            }
        }
#pragma unroll
        for (int nt = 0; nt < 2; nt++) {
            int i0 = warp * 16 + nt * 8 + tig * 2;
            float2 bb = *(const float2*)&b2[i0];
#pragma unroll
            for (int mt = 0; mt < 2; mt++) {
                float* c = c2[mt][nt];
                int r0 = mt * 16 + g;
                {
                    float pm = pm_s[r0];
                    float2 zz = *(const float2*)&z_s[r0 * ZSTR + i0];
                    float2 o;
                    o.x = (zz.x + c[0] + bb.x) * pm;
                    o.y = (zz.y + c[1] + bb.y) * pm;
                    *(float2*)&out[((size_t)(n * KNB + kbase + r0)) * PD + i0] = o;
                }
                {
                    int r1 = r0 + 8;
                    float pm = pm_s[r1];
                    float2 zz = *(const float2*)&z_s[r1 * ZSTR + i0];
                    float2 o;
                    o.x = (zz.x + c[2] + bb.x) * pm;
                    o.y = (zz.y + c[3] + bb.y) * pm;
                    *(float2*)&out[((size_t)(n * KNB + kbase + r1)) * PD + i0] = o;
                }
            }
        }
    }
}

// ---------------- launcher ----------------
extern "C" void kernel_launch(void* const* d_in, const int* in_sizes, int n_in,
                              void* d_out, int out_size) {
    const float*        x        = (const float*)d_in[0];
    const float*        pair_rep = (const float*)d_in[1];
    const unsigned int* mask     = (const unsigned int*)d_in[2];
    const int*          nbr      = (const int*)d_in[3];
    const unsigned int* slot     = (const unsigned int*)d_in[4];
    const float*        ln_g     = (const float*)d_in[5];
    const float*        ln_b     = (const float*)d_in[6];
    const float*        Wx       = (const float*)d_in[7];
    const float*        t_g      = (const float*)d_in[8];
    const float*        t_b      = (const float*)d_in[9];
    const float*        W1       = (const float*)d_in[10];
    const float*        b1       = (const float*)d_in[11];
    const float*        W2       = (const float*)d_in[12];
    const float*        b2       = (const float*)d_in[13];
    float*              out      = (float*)d_out;

    fused_k<<<PROJ_BLOCKS + PACK_BLOCKS, 256>>>(x, mask, ln_g, ln_b, Wx, W1, W2);

    cudaFuncSetAttribute(main_k, cudaFuncAttributeMaxDynamicSharedMemorySize, SM_TOT);
    main_k<<<2 * N_TOK, 256, SM_TOT>>>(pair_rep, mask, nbr, slot,
                                       t_g, t_b, b1, b2, out);
}

// round 15
// speedup vs baseline: 1.3166x; 1.2022x over previous
#include <cuda_runtime.h>
#include <cuda_bf16.h>
#include <cstdint>

#define N_TOK 4096
#define TD    384
#define KNB   64
#define PD    128
#define HD    256
#define LN_EPS 1e-5f

// ---------------- device scratch (no allocs allowed) ----------------
__device__ __align__(16) float g_proj[N_TOK * 256];   // [n][0:128]=xp1, [128:256]=xp2
// Weight fragments for mma.sync.m16n8k16 (bf16), packed as uint4 nt-pairs:
__device__ __align__(16) uint4 g_W1f4[8 * 16 * 32];   // K=128 (8 kt) x N=256 (16 np)
__device__ __align__(16) uint4 g_W2f4[16 * 8 * 32];   // K=256 (16 kt) x N=128 (8 np)
// Wx in tf32 B-fragment order for mma.m16n8k8: [48 kt][32 ng][32 lanes] float2
__device__ __align__(16) uint2 g_Wxf[48 * 32 * 32];

// bool inputs arrive as 4-byte words (int32/float32); nonzero = true.
__device__ __forceinline__ bool bval(const unsigned int* b, int i) { return b[i] != 0u; }

__device__ __forceinline__ uint32_t pack2bf(float a, float b) {
    __nv_bfloat162 t = __floats2bfloat162_rn(a, b);
    return *reinterpret_cast<uint32_t*>(&t);
}

__device__ __forceinline__ uint32_t tf32r(float f) {
    uint32_t o;
    asm("cvt.rna.tf32.f32 %0, %1;" : "=r"(o) : "f"(f));
    return o;
}

__device__ __forceinline__ uint32_t smem_u32(const void* p) {
    uint32_t a;
    asm("{ .reg .u64 t; cvta.to.shared.u64 t, %1; cvt.u32.u64 %0, t; }" : "=r"(a) : "l"(p));
    return a;
}

__device__ __forceinline__ void ldsm_x4(uint32_t* a, uint32_t addr) {
    asm volatile("ldmatrix.sync.aligned.m8n8.x4.shared.b16 {%0,%1,%2,%3}, [%4];"
                 : "=r"(a[0]), "=r"(a[1]), "=r"(a[2]), "=r"(a[3]) : "r"(addr));
}

__device__ __forceinline__ void mma16816(float* c, const uint32_t* a, uint32_t b0, uint32_t b1) {
    asm volatile(
        "mma.sync.aligned.m16n8k16.row.col.f32.bf16.bf16.f32 "
        "{%0,%1,%2,%3}, {%4,%5,%6,%7}, {%8,%9}, {%0,%1,%2,%3};"
        : "+f"(c[0]), "+f"(c[1]), "+f"(c[2]), "+f"(c[3])
        : "r"(a[0]), "r"(a[1]), "r"(a[2]), "r"(a[3]), "r"(b0), "r"(b1));
}

__device__ __forceinline__ void mma1688_tf32(float* c, const uint32_t* a, uint32_t b0, uint32_t b1) {
    asm volatile(
        "mma.sync.aligned.m16n8k8.row.col.f32.tf32.tf32.f32 "
        "{%0,%1,%2,%3}, {%4,%5,%6,%7}, {%8,%9}, {%0,%1,%2,%3};"
        : "+f"(c[0]), "+f"(c[1]), "+f"(c[2]), "+f"(c[3])
        : "r"(a[0]), "r"(a[1]), "r"(a[2]), "r"(a[3]), "r"(b0), "r"(b1));
}

// ---------------- kernel 1: tf32 tensor-core proj + weight packing ---------
// blocks [0,256): proj, 16 token-rows each, mma.m16n8k8.tf32
// blocks [256,288): pack W1/W2 bf16 fragments + Wx tf32 fragments
#define PROJ_ROWS   16
#define PROJ_BLOCKS (N_TOK / PROJ_ROWS)    // 256
#define PACK_BLOCKS 32
#define XS_STR      388    // floats/row; mod 32 == 4 -> conflict-free A-frag loads

__global__ __launch_bounds__(256) void fused_k(const float* __restrict__ x,
                                               const unsigned int* __restrict__ mask,
                                               const float* __restrict__ ln_g,
                                               const float* __restrict__ ln_b,
                                               const float* __restrict__ Wx,
                                               const float* __restrict__ W1,
                                               const float* __restrict__ W2) {
    __shared__ float xs[PROJ_ROWS * XS_STR];   // 24.8 KB
    int tid = threadIdx.x;
    int warp = tid >> 5, lane = tid & 31;
    int g = lane >> 2, tig = lane & 3;

    if (blockIdx.x >= PROJ_BLOCKS) {
        int t0 = (blockIdx.x - PROJ_BLOCKS) * 256 + tid;
        int stride = PACK_BLOCKS * 256;
        // ---- W1/W2 bf16 fragment packing (unchanged, proven) ----
        for (int e = t0; e < 8 * 16 * 32; e += stride) {
            int ln = e & 31, np = (e >> 5) & 15, kt = e >> 9;
            int tg2 = ln & 3, gg = ln >> 2;
            int j0 = (2 * np) * 8 + gg;
            int j1 = (2 * np + 1) * 8 + gg;
            int k0 = kt * 16 + tg2 * 2;
            g_W1f4[e] = make_uint4(
                pack2bf(W1[k0 * HD + j0], W1[(k0 + 1) * HD + j0]),
                pack2bf(W1[(k0 + 8) * HD + j0], W1[(k0 + 9) * HD + j0]),
                pack2bf(W1[k0 * HD + j1], W1[(k0 + 1) * HD + j1]),
                pack2bf(W1[(k0 + 8) * HD + j1], W1[(k0 + 9) * HD + j1]));
        }
        for (int e = t0; e < 16 * 8 * 32; e += stride) {
            int ln = e & 31, np = (e >> 5) & 7, kt = e >> 8;
            int tg2 = ln & 3, gg = ln >> 2;
            int i0 = (2 * np) * 8 + gg;
            int i1 = (2 * np + 1) * 8 + gg;
            int k0 = kt * 16 + tg2 * 2;
            g_W2f4[e] = make_uint4(
                pack2bf(W2[k0 * PD + i0], W2[(k0 + 1) * PD + i0]),
                pack2bf(W2[(k0 + 8) * PD + i0], W2[(k0 + 9) * PD + i0]),
                pack2bf(W2[k0 * PD + i1], W2[(k0 + 1) * PD + i1]),
                pack2bf(W2[(k0 + 8) * PD + i1], W2[(k0 + 9) * PD + i1]));
        }
        // ---- Wx tf32 B-fragment packing (RNA-rounded once here) ----
        // b0 = Wx[kt*8 + (lane&3)][n], b1 = Wx[kt*8 + (lane&3) + 4][n],
        // n = ng*8 + (lane>>2)
        for (int e = t0; e < 48 * 32 * 32; e += stride) {
            int ln = e & 31, ng = (e >> 5) & 31, kt = e >> 10;
            int n  = ng * 8 + (ln >> 2);
            int k0 = kt * 8 + (ln & 3);
            g_Wxf[e] = make_uint2(tf32r(Wx[k0 * 256 + n]),
                                  tf32r(Wx[(k0 + 4) * 256 + n]));
        }
        return;
    }

    // ---- proj = LN(x*mask) @ Wx via tf32 mma ----
    int n0 = blockIdx.x * PROJ_ROWS;
    for (int i = tid; i < PROJ_ROWS * TD; i += 256) {
        int r = i / TD, c = i - r * TD;
        float mf = bval(mask, n0 + r) ? 1.0f : 0.0f;
        xs[r * XS_STR + c] = x[(size_t)n0 * TD + i] * mf;
    }
    __syncthreads();

    // LN: warp w handles rows 2w, 2w+1 ; store RNA-rounded tf32 values
    {
#pragma unroll
        for (int rr = 0; rr < 2; rr++) {
            int r = warp * 2 + rr;
            float v[12];
            float s = 0.0f, s2 = 0.0f;
#pragma unroll
            for (int q = 0; q < 12; q++) {
                v[q] = xs[r * XS_STR + lane + q * 32];
                s += v[q]; s2 += v[q] * v[q];
            }
#pragma unroll
            for (int o = 16; o; o >>= 1) {
                s  += __shfl_xor_sync(0xffffffffu, s, o);
                s2 += __shfl_xor_sync(0xffffffffu, s2, o);
            }
            float mu = s * (1.0f / (float)TD);
            float rstd = rsqrtf(s2 * (1.0f / (float)TD) - mu * mu + LN_EPS);
#pragma unroll
            for (int q = 0; q < 12; q++) {
                int t = lane + q * 32;
                float val = (v[q] - mu) * rstd * ln_g[t] + ln_b[t];
                xs[r * XS_STR + t] = __uint_as_float(tf32r(val));
            }
        }
    }
    __syncthreads();

    // GEMM: warp covers 32 N-cols (4 n-tiles); M=16 (1 m-tile); K=384 (48 kt)
    {
        float c[4][4];
#pragma unroll
        for (int nt = 0; nt < 4; nt++)
#pragma unroll
            for (int q = 0; q < 4; q++) c[nt][q] = 0.0f;

#pragma unroll 4
        for (int kt = 0; kt < 48; kt++) {
            // A fragment (m16n8k8.tf32): rows g/g+8, cols tig/tig+4 of k-tile
            const float* xa = xs + kt * 8;
            uint32_t a[4];
            a[0] = __float_as_uint(xa[g * XS_STR + tig]);
            a[1] = __float_as_uint(xa[(g + 8) * XS_STR + tig]);
            a[2] = __float_as_uint(xa[g * XS_STR + tig + 4]);
            a[3] = __float_as_uint(xa[(g + 8) * XS_STR + tig + 4]);
#pragma unroll
            for (int nt = 0; nt < 4; nt++) {
                uint2 b = g_Wxf[((kt * 32) + (warp * 4 + nt)) * 32 + lane];
                mma1688_tf32(c[nt], a, b.x, b.y);
            }
        }
#pragma unroll
        for (int nt = 0; nt < 4; nt++) {
            int col = warp * 32 + nt * 8 + tig * 2;
            float2 o0 = make_float2(c[nt][0], c[nt][1]);
            float2 o1 = make_float2(c[nt][2], c[nt][3]);
            *(float2*)&g_proj[(size_t)(n0 + g) * 256 + col]     = o0;
            *(float2*)&g_proj[(size_t)(n0 + g + 8) * 256 + col] = o1;
        }
    }
}

// ---------------- kernel 2: fused pair update + transition ------------------
// FROZEN: exact R11/R13/R14 configuration (166.8-167.4 us, 4 consistent runs).
// One CTA = 32 pair-rows. 256 threads = 8 warps. grid = 8192.
#define SM_Z    0
#define SM_ZLN  16896
#define SM_H    25600
#define SM_XP2  42496
#define SM_PM   43008
#define SM_IDX  43136
#define SM_TOT  43264
#define ZSTR    132
#define LSTR    136
#define HSTR    264

__global__ __launch_bounds__(256, 4) void main_k(const float* __restrict__ pair_rep,
                                                 const unsigned int* __restrict__ mask,
                                                 const int* __restrict__ nbr,
                                                 const unsigned int* __restrict__ slot,
                                                 const float* __restrict__ t_g,
                                                 const float* __restrict__ t_b,
                                                 const float* __restrict__ b1,
                                                 const float* __restrict__ b2,
                                                 float* __restrict__ out) {
    extern __shared__ char smb[];
    float* z_s   = (float*)(smb + SM_Z);
    char*  zln_b = smb + SM_ZLN;
    char*  h_b   = smb + SM_H;
    float* xp2_s = (float*)(smb + SM_XP2);
    float* pm_s  = (float*)(smb + SM_PM);
    int*   idx_s = (int*)(smb + SM_IDX);

    int tid  = threadIdx.x;
    int warp = tid >> 5, lane = tid & 31;
    int g    = lane >> 2, tig = lane & 3;
    int n     = blockIdx.x >> 1;
    int kbase = (blockIdx.x & 1) * 32;

    if (tid < 128) {
        xp2_s[tid] = g_proj[n * 256 + 128 + tid];
    } else if (tid < 160) {
        int r = tid - 128;
        int k = kbase + r;
        int idx = nbr[n * KNB + k];
        idx_s[r] = idx;
        bool pm = bval(mask, n) && bval(mask, idx) && bval(slot, n * KNB + k);
        pm_s[r] = pm ? 1.0f : 0.0f;
    }
    __syncthreads();

    // ---- z = (pair_rep + xp2 + xp1[nbr]) * pm ----
    {
        int pc = lane * 4;
        int rb = warp;
#pragma unroll
        for (int it = 0; it < 4; it++) {
            int r = it * 8 + rb;
            const float4 pr = *(const float4*)&pair_rep[((size_t)(n * KNB + kbase + r)) * PD + pc];
            const float4 xj = *(const float4*)&g_proj[idx_s[r] * 256 + pc];
            const float4 xo = *(const float4*)&xp2_s[pc];
            float pm = pm_s[r];
            float4 z;
            z.x = (pr.x + xo.x + xj.x) * pm;
            z.y = (pr.y + xo.y + xj.y) * pm;
            z.z = (pr.z + xo.z + xj.z) * pm;
            z.w = (pr.w + xo.w + xj.w) * pm;
            *(float4*)&z_s[r * ZSTR + pc] = z;
        }
    }
    __syncthreads();

    // ---- LayerNorm(z) -> zln (bf16), single-pass sum/sumsq ----
    {
        float4 tg4 = *(const float4*)&t_g[4 * lane];
        float4 tb4 = *(const float4*)&t_b[4 * lane];
#pragma unroll
        for (int rr = 0; rr < 4; rr++) {
            int r = warp * 4 + rr;
            float4 v = *(const float4*)&z_s[r * ZSTR + 4 * lane];
            float s  = v.x + v.y + v.z + v.w;
            float s2 = v.x * v.x + v.y * v.y + v.z * v.z + v.w * v.w;
#pragma unroll
            for (int o = 16; o; o >>= 1) {
                s  += __shfl_xor_sync(0xffffffffu, s, o);
                s2 += __shfl_xor_sync(0xffffffffu, s2, o);
            }
            float mu  = s * (1.0f / 128.0f);
            float var = s2 * (1.0f / 128.0f) - mu * mu;
            float rstd = rsqrtf(var + LN_EPS);
            uint2 pk;
            pk.x = pack2bf((v.x - mu) * rstd * tg4.x + tb4.x,
                           (v.y - mu) * rstd * tg4.y + tb4.y);
            pk.y = pack2bf((v.z - mu) * rstd * tg4.z + tb4.z,
                           (v.w - mu) * rstd * tg4.w + tb4.w);
            *(uint2*)(zln_b + r * (LSTR * 2) + 8 * lane) = pk;
        }
    }
    __syncthreads();

    // ---- phase 1: h = relu(zln @ W1 + b1) ; warp covers 32 N-cols ----
    {
        uint32_t zln_u = smem_u32(zln_b);
        float c1[2][4][4];
#pragma unroll
        for (int mt = 0; mt < 2; mt++)
#pragma unroll
            for (int nt = 0; nt < 4; nt++)
#pragma unroll
                for (int q = 0; q < 4; q++) c1[mt][nt][q] = 0.0f;

#pragma unroll 2
        for (int kt = 0; kt < 8; kt++) {
            uint32_t a0[4], a1[4];
            {
                uint32_t base = zln_u + ((lane & 15) * LSTR + kt * 16 + (lane >> 4) * 8) * 2;
                ldsm_x4(a0, base);
                ldsm_x4(a1, base + 16 * LSTR * 2);
            }
#pragma unroll
            for (int np = 0; np < 2; np++) {
                uint4 w = g_W1f4[((kt * 16) + (warp * 2 + np)) * 32 + lane];
                mma16816(c1[0][2 * np],     a0, w.x, w.y);
                mma16816(c1[1][2 * np],     a1, w.x, w.y);
                mma16816(c1[0][2 * np + 1], a0, w.z, w.w);
                mma16816(c1[1][2 * np + 1], a1, w.z, w.w);
            }
        }
#pragma unroll
        for (int nt = 0; nt < 4; nt++) {
            int j0 = warp * 32 + nt * 8 + tig * 2;
            float2 bb = *(const float2*)&b1[j0];
#pragma unroll
            for (int mt = 0; mt < 2; mt++) {
                int r0 = mt * 16 + g;
                float* c = c1[mt][nt];
                *(uint32_t*)(h_b + r0 * (HSTR * 2) + j0 * 2) =
                    pack2bf(fmaxf(c[0] + bb.x, 0.0f), fmaxf(c[1] + bb.y, 0.0f));
                *(uint32_t*)(h_b + (r0 + 8) * (HSTR * 2) + j0 * 2) =
                    pack2bf(fmaxf(c[2] + bb.x, 0.0f), fmaxf(c[3] + bb.y, 0.0f));
            }
        }
    }
    __syncthreads();

    // ---- phase 2: out = (z + h @ W2 + b2) * pm ; warp covers 16 N-cols ----
    {
        uint32_t h_u = smem_u32(h_b);
        float c2[2][2][4];
#pragma unroll
        for (int mt = 0; mt < 2; mt++)
#pragma unroll
            for (int nt = 0; nt < 2; nt++)
#pragma unroll
                for (int q = 0; q < 4; q++) c2[mt][nt][q] = 0.0f;

#pragma unroll 4
        for (int kt = 0; kt < 16; kt++) {
            uint32_t a0[4], a1[4];
            {
                uint32_t base = h_u + ((lane & 15) * HSTR + kt * 16 + (lane >> 4) * 8) * 2;
                ldsm_x4(a0, base);
                ldsm_x4(a1, base + 16 * HSTR * 2);
            }
            {
                uint4 w = g_W2f4[((kt * 8) + warp) * 32 + lane];
                mma16816(c2[0][0], a0, w.x, w.y);
                mma16816(c2[1][0], a1, w.x, w.y);
                mma16816(c2[0][1], a0, w.z, w.w);
                mma16816(c2[1][1], a1, w.z, w.w);
            }
        }
#pragma unroll
        for (int nt = 0; nt < 2; nt++) {
            int i0 = warp * 16 + nt * 8 + tig * 2;
            float2 bb = *(const float2*)&b2[i0];
#pragma unroll
            for (int mt = 0; mt < 2; mt++) {
                float* c = c2[mt][nt];
                int r0 = mt * 16 + g;
                {
                    float pm = pm_s[r0];
                    float2 zz = *(const float2*)&z_s[r0 * ZSTR + i0];
                    float2 o;
                    o.x = (zz.x + c[0] + bb.x) * pm;
                    o.y = (zz.y + c[1] + bb.y) * pm;
                    *(float2*)&out[((size_t)(n * KNB + kbase + r0)) * PD + i0] = o;
                }
                {
                    int r1 = r0 + 8;
                    float pm = pm_s[r1];
                    float2 zz = *(const float2*)&z_s[r1 * ZSTR + i0];
                    float2 o;
                    o.x = (zz.x + c[2] + bb.x) * pm;
                    o.y = (zz.y + c[3] + bb.y) * pm;
                    *(float2*)&out[((size_t)(n * KNB + kbase + r1)) * PD + i0] = o;
                }
            }
        }
    }
}

// ---------------- launcher ----------------
extern "C" void kernel_launch(void* const* d_in, const int* in_sizes, int n_in,
                              void* d_out, int out_size) {
    const float*        x        = (const float*)d_in[0];
    const float*        pair_rep = (const float*)d_in[1];
    const unsigned int* mask     = (const unsigned int*)d_in[2];
    const int*          nbr      = (const int*)d_in[3];
    const unsigned int* slot     = (const unsigned int*)d_in[4];
    const float*        ln_g     = (const float*)d_in[5];
    const float*        ln_b     = (const float*)d_in[6];
    const float*        Wx       = (const float*)d_in[7];
    const float*        t_g      = (const float*)d_in[8];
    const float*        t_b      = (const float*)d_in[9];
    const float*        W1       = (const float*)d_in[10];
    const float*        b1       = (const float*)d_in[11];
    const float*        W2       = (const float*)d_in[12];
    const float*        b2       = (const float*)d_in[13];
    float*              out      = (float*)d_out;

    fused_k<<<PROJ_BLOCKS + PACK_BLOCKS, 256>>>(x, mask, ln_g, ln_b, Wx, W1, W2);

    cudaFuncSetAttribute(main_k, cudaFuncAttributeMaxDynamicSharedMemorySize, SM_TOT);
    main_k<<<2 * N_TOK, 256, SM_TOT>>>(pair_rep, mask, nbr, slot,
                                       t_g, t_b, b1, b2, out);
}

// round 16
// speedup vs baseline: 1.3294x; 1.0098x over previous
#include <cuda_runtime.h>
#include <cuda_bf16.h>
#include <cstdint>

#define N_TOK 4096
#define TD    384
#define KNB   64
#define PD    128
#define HD    256
#define LN_EPS 1e-5f

// ---------------- device scratch (no allocs allowed) ----------------
__device__ __align__(16) float g_proj[N_TOK * 256];   // [n][0:128]=xp1, [128:256]=xp2
// Weight fragments for mma.sync.m16n8k16 (bf16), packed as uint4 nt-pairs:
__device__ __align__(16) uint4 g_W1f4[8 * 16 * 32];   // K=128 (8 kt) x N=256 (16 np)
__device__ __align__(16) uint4 g_W2f4[16 * 8 * 32];   // K=256 (16 kt) x N=128 (8 np)
// Wx in tf32 B-fragment order for mma.m16n8k8: [48 kt][32 ng][32 lanes] float2
__device__ __align__(16) uint2 g_Wxf[48 * 32 * 32];

// bool inputs arrive as 4-byte words (int32/float32); nonzero = true.
__device__ __forceinline__ bool bval(const unsigned int* b, int i) { return b[i] != 0u; }

__device__ __forceinline__ uint32_t pack2bf(float a, float b) {
    __nv_bfloat162 t = __floats2bfloat162_rn(a, b);
    return *reinterpret_cast<uint32_t*>(&t);
}

__device__ __forceinline__ uint32_t tf32r(float f) {
    uint32_t o;
    asm("cvt.rna.tf32.f32 %0, %1;" : "=r"(o) : "f"(f));
    return o;
}

__device__ __forceinline__ uint32_t smem_u32(const void* p) {
    uint32_t a;
    asm("{ .reg .u64 t; cvta.to.shared.u64 t, %1; cvt.u32.u64 %0, t; }" : "=r"(a) : "l"(p));
    return a;
}

__device__ __forceinline__ void ldsm_x4(uint32_t* a, uint32_t addr) {
    asm volatile("ldmatrix.sync.aligned.m8n8.x4.shared.b16 {%0,%1,%2,%3}, [%4];"
                 : "=r"(a[0]), "=r"(a[1]), "=r"(a[2]), "=r"(a[3]) : "r"(addr));
}

__device__ __forceinline__ void mma16816(float* c, const uint32_t* a, uint32_t b0, uint32_t b1) {
    asm volatile(
        "mma.sync.aligned.m16n8k16.row.col.f32.bf16.bf16.f32 "
        "{%0,%1,%2,%3}, {%4,%5,%6,%7}, {%8,%9}, {%0,%1,%2,%3};"
        : "+f"(c[0]), "+f"(c[1]), "+f"(c[2]), "+f"(c[3])
        : "r"(a[0]), "r"(a[1]), "r"(a[2]), "r"(a[3]), "r"(b0), "r"(b1));
}

__device__ __forceinline__ void mma1688_tf32(float* c, const uint32_t* a, uint32_t b0, uint32_t b1) {
    asm volatile(
        "mma.sync.aligned.m16n8k8.row.col.f32.tf32.tf32.f32 "
        "{%0,%1,%2,%3}, {%4,%5,%6,%7}, {%8,%9}, {%0,%1,%2,%3};"
        : "+f"(c[0]), "+f"(c[1]), "+f"(c[2]), "+f"(c[3])
        : "r"(a[0]), "r"(a[1]), "r"(a[2]), "r"(a[3]), "r"(b0), "r"(b1));
}

// ---------------- kernel 1: tf32 tensor-core proj + weight packing ---------
// PROVEN (R15): rest = 18.3 us total.
#define PROJ_ROWS   16
#define PROJ_BLOCKS (N_TOK / PROJ_ROWS)    // 256
#define PACK_BLOCKS 32
#define XS_STR      388    // floats/row; mod 32 == 4 -> conflict-free A-frag loads

__global__ __launch_bounds__(256) void fused_k(const float* __restrict__ x,
                                               const unsigned int* __restrict__ mask,
                                               const float* __restrict__ ln_g,
                                               const float* __restrict__ ln_b,
                                               const float* __restrict__ Wx,
                                               const float* __restrict__ W1,
                                               const float* __restrict__ W2) {
    __shared__ float xs[PROJ_ROWS * XS_STR];   // 24.8 KB
    int tid = threadIdx.x;
    int warp = tid >> 5, lane = tid & 31;
    int g = lane >> 2, tig = lane & 3;

    if (blockIdx.x >= PROJ_BLOCKS) {
        int t0 = (blockIdx.x - PROJ_BLOCKS) * 256 + tid;
        int stride = PACK_BLOCKS * 256;
        // ---- W1/W2 bf16 fragment packing ----
        for (int e = t0; e < 8 * 16 * 32; e += stride) {
            int ln = e & 31, np = (e >> 5) & 15, kt = e >> 9;
            int tg2 = ln & 3, gg = ln >> 2;
            int j0 = (2 * np) * 8 + gg;
            int j1 = (2 * np + 1) * 8 + gg;
            int k0 = kt * 16 + tg2 * 2;
            g_W1f4[e] = make_uint4(
                pack2bf(W1[k0 * HD + j0], W1[(k0 + 1) * HD + j0]),
                pack2bf(W1[(k0 + 8) * HD + j0], W1[(k0 + 9) * HD + j0]),
                pack2bf(W1[k0 * HD + j1], W1[(k0 + 1) * HD + j1]),
                pack2bf(W1[(k0 + 8) * HD + j1], W1[(k0 + 9) * HD + j1]));
        }
        for (int e = t0; e < 16 * 8 * 32; e += stride) {
            int ln = e & 31, np = (e >> 5) & 7, kt = e >> 8;
            int tg2 = ln & 3, gg = ln >> 2;
            int i0 = (2 * np) * 8 + gg;
            int i1 = (2 * np + 1) * 8 + gg;
            int k0 = kt * 16 + tg2 * 2;
            g_W2f4[e] = make_uint4(
                pack2bf(W2[k0 * PD + i0], W2[(k0 + 1) * PD + i0]),
                pack2bf(W2[(k0 + 8) * PD + i0], W2[(k0 + 9) * PD + i0]),
                pack2bf(W2[k0 * PD + i1], W2[(k0 + 1) * PD + i1]),
                pack2bf(W2[(k0 + 8) * PD + i1], W2[(k0 + 9) * PD + i1]));
        }
        // ---- Wx tf32 B-fragment packing (RNA-rounded once here) ----
        for (int e = t0; e < 48 * 32 * 32; e += stride) {
            int ln = e & 31, ng = (e >> 5) & 31, kt = e >> 10;
            int n  = ng * 8 + (ln >> 2);
            int k0 = kt * 8 + (ln & 3);
            g_Wxf[e] = make_uint2(tf32r(Wx[k0 * 256 + n]),
                                  tf32r(Wx[(k0 + 4) * 256 + n]));
        }
        return;
    }

    // ---- proj = LN(x*mask) @ Wx via tf32 mma ----
    int n0 = blockIdx.x * PROJ_ROWS;
    for (int i = tid; i < PROJ_ROWS * TD; i += 256) {
        int r = i / TD, c = i - r * TD;
        float mf = bval(mask, n0 + r) ? 1.0f : 0.0f;
        xs[r * XS_STR + c] = x[(size_t)n0 * TD + i] * mf;
    }
    __syncthreads();

    {
#pragma unroll
        for (int rr = 0; rr < 2; rr++) {
            int r = warp * 2 + rr;
            float v[12];
            float s = 0.0f, s2 = 0.0f;
#pragma unroll
            for (int q = 0; q < 12; q++) {
                v[q] = xs[r * XS_STR + lane + q * 32];
                s += v[q]; s2 += v[q] * v[q];
            }
#pragma unroll
            for (int o = 16; o; o >>= 1) {
                s  += __shfl_xor_sync(0xffffffffu, s, o);
                s2 += __shfl_xor_sync(0xffffffffu, s2, o);
            }
            float mu = s * (1.0f / (float)TD);
            float rstd = rsqrtf(s2 * (1.0f / (float)TD) - mu * mu + LN_EPS);
#pragma unroll
            for (int q = 0; q < 12; q++) {
                int t = lane + q * 32;
                float val = (v[q] - mu) * rstd * ln_g[t] + ln_b[t];
                xs[r * XS_STR + t] = __uint_as_float(tf32r(val));
            }
        }
    }
    __syncthreads();

    {
        float c[4][4];
#pragma unroll
        for (int nt = 0; nt < 4; nt++)
#pragma unroll
            for (int q = 0; q < 4; q++) c[nt][q] = 0.0f;

#pragma unroll 4
        for (int kt = 0; kt < 48; kt++) {
            const float* xa = xs + kt * 8;
            uint32_t a[4];
            a[0] = __float_as_uint(xa[g * XS_STR + tig]);
            a[1] = __float_as_uint(xa[(g + 8) * XS_STR + tig]);
            a[2] = __float_as_uint(xa[g * XS_STR + tig + 4]);
            a[3] = __float_as_uint(xa[(g + 8) * XS_STR + tig + 4]);
#pragma unroll
            for (int nt = 0; nt < 4; nt++) {
                uint2 b = g_Wxf[((kt * 32) + (warp * 4 + nt)) * 32 + lane];
                mma1688_tf32(c[nt], a, b.x, b.y);
            }
        }
#pragma unroll
        for (int nt = 0; nt < 4; nt++) {
            int col = warp * 32 + nt * 8 + tig * 2;
            float2 o0 = make_float2(c[nt][0], c[nt][1]);
            float2 o1 = make_float2(c[nt][2], c[nt][3]);
            *(float2*)&g_proj[(size_t)(n0 + g) * 256 + col]     = o0;
            *(float2*)&g_proj[(size_t)(n0 + g + 8) * 256 + col] = o1;
        }
    }
}

// ---------------- kernel 2: fused pair update + transition ------------------
// R15 base (167 us) + z-build/LN fusion: the warp that builds a row LNs it
// inline from registers (bit-identical accumulation order), removing the
// 16 KB z_s re-read and one __syncthreads. Warps/regs/occupancy unchanged.
#define SM_Z    0
#define SM_ZLN  16896
#define SM_H    25600
#define SM_XP2  42496
#define SM_PM   43008
#define SM_IDX  43136
#define SM_TOT  43264
#define ZSTR    132
#define LSTR    136
#define HSTR    264

__global__ __launch_bounds__(256, 4) void main_k(const float* __restrict__ pair_rep,
                                                 const unsigned int* __restrict__ mask,
                                                 const int* __restrict__ nbr,
                                                 const unsigned int* __restrict__ slot,
                                                 const float* __restrict__ t_g,
                                                 const float* __restrict__ t_b,
                                                 const float* __restrict__ b1,
                                                 const float* __restrict__ b2,
                                                 float* __restrict__ out) {
    extern __shared__ char smb[];
    float* z_s   = (float*)(smb + SM_Z);
    char*  zln_b = smb + SM_ZLN;
    char*  h_b   = smb + SM_H;
    float* xp2_s = (float*)(smb + SM_XP2);
    float* pm_s  = (float*)(smb + SM_PM);
    int*   idx_s = (int*)(smb + SM_IDX);

    int tid  = threadIdx.x;
    int warp = tid >> 5, lane = tid & 31;
    int g    = lane >> 2, tig = lane & 3;
    int n     = blockIdx.x >> 1;
    int kbase = (blockIdx.x & 1) * 32;

    if (tid < 128) {
        xp2_s[tid] = g_proj[n * 256 + 128 + tid];
    } else if (tid < 160) {
        int r = tid - 128;
        int k = kbase + r;
        int idx = nbr[n * KNB + k];
        idx_s[r] = idx;
        bool pm = bval(mask, n) && bval(mask, idx) && bval(slot, n * KNB + k);
        pm_s[r] = pm ? 1.0f : 0.0f;
    }
    __syncthreads();

    // ---- fused: z = (pair_rep + xp2 + xp1[nbr]) * pm ; LN(z) -> zln bf16 ----
    {
        int pc = lane * 4;
        float4 xo  = *(const float4*)&xp2_s[pc];        // loop-invariant, hoisted
        float4 tg4 = *(const float4*)&t_g[pc];
        float4 tb4 = *(const float4*)&t_b[pc];
#pragma unroll
        for (int it = 0; it < 4; it++) {
            int r = it * 8 + warp;
            const float4 pr = *(const float4*)&pair_rep[((size_t)(n * KNB + kbase + r)) * PD + pc];
            const float4 xj = *(const float4*)&g_proj[idx_s[r] * 256 + pc];
            float pm = pm_s[r];
            float4 z;
            z.x = (pr.x + xo.x + xj.x) * pm;
            z.y = (pr.y + xo.y + xj.y) * pm;
            z.z = (pr.z + xo.z + xj.z) * pm;
            z.w = (pr.w + xo.w + xj.w) * pm;
            *(float4*)&z_s[r * ZSTR + pc] = z;          // kept for phase-2 residual

            // LN inline (same quad-sum + shuffle tree as frozen version)
            float s  = z.x + z.y + z.z + z.w;
            float s2 = z.x * z.x + z.y * z.y + z.z * z.z + z.w * z.w;
#pragma unroll
            for (int o = 16; o; o >>= 1) {
                s  += __shfl_xor_sync(0xffffffffu, s, o);
                s2 += __shfl_xor_sync(0xffffffffu, s2, o);
            }
            float mu  = s * (1.0f / 128.0f);
            float var = s2 * (1.0f / 128.0f) - mu * mu;
            float rstd = rsqrtf(var + LN_EPS);
            uint2 pk;
            pk.x = pack2bf((z.x - mu) * rstd * tg4.x + tb4.x,
                           (z.y - mu) * rstd * tg4.y + tb4.y);
            pk.y = pack2bf((z.z - mu) * rstd * tg4.z + tb4.z,
                           (z.w - mu) * rstd * tg4.w + tb4.w);
            *(uint2*)(zln_b + r * (LSTR * 2) + 8 * lane) = pk;
        }
    }
    __syncthreads();

    // ---- phase 1: h = relu(zln @ W1 + b1) ; warp covers 32 N-cols ----
    {
        uint32_t zln_u = smem_u32(zln_b);
        float c1[2][4][4];
#pragma unroll
        for (int mt = 0; mt < 2; mt++)
#pragma unroll
            for (int nt = 0; nt < 4; nt++)
#pragma unroll
                for (int q = 0; q < 4; q++) c1[mt][nt][q] = 0.0f;

#pragma unroll 2
        for (int kt = 0; kt < 8; kt++) {
            uint32_t a0[4], a1[4];
            {
                uint32_t base = zln_u + ((lane & 15) * LSTR + kt * 16 + (lane >> 4) * 8) * 2;
                ldsm_x4(a0, base);
                ldsm_x4(a1, base + 16 * LSTR * 2);
            }
#pragma unroll
            for (int np = 0; np < 2; np++) {
                uint4 w = g_W1f4[((kt * 16) + (warp * 2 + np)) * 32 + lane];
                mma16816(c1[0][2 * np],     a0, w.x, w.y);
                mma16816(c1[1][2 * np],     a1, w.x, w.y);
                mma16816(c1[0][2 * np + 1], a0, w.z, w.w);
                mma16816(c1[1][2 * np + 1], a1, w.z, w.w);
            }
        }
#pragma unroll
        for (int nt = 0; nt < 4; nt++) {
            int j0 = warp * 32 + nt * 8 + tig * 2;
            float2 bb = *(const float2*)&b1[j0];
#pragma unroll
            for (int mt = 0; mt < 2; mt++) {
                int r0 = mt * 16 + g;
                float* c = c1[mt][nt];
                *(uint32_t*)(h_b + r0 * (HSTR * 2) + j0 * 2) =
                    pack2bf(fmaxf(c[0] + bb.x, 0.0f), fmaxf(c[1] + bb.y, 0.0f));
                *(uint32_t*)(h_b + (r0 + 8) * (HSTR * 2) + j0 * 2) =
                    pack2bf(fmaxf(c[2] + bb.x, 0.0f), fmaxf(c[3] + bb.y, 0.0f));
            }
        }
    }
    __syncthreads();

    // ---- phase 2: out = (z + h @ W2 + b2) * pm ; warp covers 16 N-cols ----
    {
        uint32_t h_u = smem_u32(h_b);
        float c2[2][2][4];
#pragma unroll
        for (int mt = 0; mt < 2; mt++)
#pragma unroll
            for (int nt = 0; nt < 2; nt++)
#pragma unroll
                for (int q = 0; q < 4; q++) c2[mt][nt][q] = 0.0f;

#pragma unroll 4
        for (int kt = 0; kt < 16; kt++) {
            uint32_t a0[4], a1[4];
            {
                uint32_t base = h_u + ((lane & 15) * HSTR + kt * 16 + (lane >> 4) * 8) * 2;
                ldsm_x4(a0, base);
                ldsm_x4(a1, base + 16 * HSTR * 2);
            }
            {
                uint4 w = g_W2f4[((kt * 8) + warp) * 32 + lane];
                mma16816(c2[0][0], a0, w.x, w.y);
                mma16816(c2[1][0], a1, w.x, w.y);
                mma16816(c2[0][1], a0, w.z, w.w);
                mma16816(c2[1][1], a1, w.z, w.w);
            }
        }
#pragma unroll
        for (int nt = 0; nt < 2; nt++) {
            int i0 = warp * 16 + nt * 8 + tig * 2;
            float2 bb = *(const float2*)&b2[i0];
#pragma unroll
            for (int mt = 0; mt < 2; mt++) {
                float* c = c2[mt][nt];
                int r0 = mt * 16 + g;
                {
                    float pm = pm_s[r0];
                    float2 zz = *(const float2*)&z_s[r0 * ZSTR + i0];
                    float2 o;
                    o.x = (zz.x + c[0] + bb.x) * pm;
                    o.y = (zz.y + c[1] + bb.y) * pm;
                    *(float2*)&out[((size_t)(n * KNB + kbase + r0)) * PD + i0] = o;
                }
                {
                    int r1 = r0 + 8;
                    float pm = pm_s[r1];
                    float2 zz = *(const float2*)&z_s[r1 * ZSTR + i0];
                    float2 o;
                    o.x = (zz.x + c[2] + bb.x) * pm;
                    o.y = (zz.y + c[3] + bb.y) * pm;
                    *(float2*)&out[((size_t)(n * KNB + kbase + r1)) * PD + i0] = o;
                }
            }
        }
    }
}

// ---------------- launcher ----------------
extern "C" void kernel_launch(void* const* d_in, const int* in_sizes, int n_in,
                              void* d_out, int out_size) {
    const float*        x        = (const float*)d_in[0];
    const float*        pair_rep = (const float*)d_in[1];
    const unsigned int* mask     = (const unsigned int*)d_in[2];
    const int*          nbr      = (const int*)d_in[3];
    const unsigned int* slot     = (const unsigned int*)d_in[4];
    const float*        ln_g     = (const float*)d_in[5];
    const float*        ln_b     = (const float*)d_in[6];
    const float*        Wx       = (const float*)d_in[7];
    const float*        t_g      = (const float*)d_in[8];
    const float*        t_b      = (const float*)d_in[9];
    const float*        W1       = (const float*)d_in[10];
    const float*        b1       = (const float*)d_in[11];
    const float*        W2       = (const float*)d_in[12];
    const float*        b2       = (const float*)d_in[13];
    float*              out      = (float*)d_out;

    fused_k<<<PROJ_BLOCKS + PACK_BLOCKS, 256>>>(x, mask, ln_g, ln_b, Wx, W1, W2);

    cudaFuncSetAttribute(main_k, cudaFuncAttributeMaxDynamicSharedMemorySize, SM_TOT);
    main_k<<<2 * N_TOK, 256, SM_TOT>>>(pair_rep, mask, nbr, slot,
                                       t_g, t_b, b1, b2, out);
}